// round 2
// baseline (speedup 1.0000x reference)
#include <cuda_runtime.h>
#include <cstdint>

// Problem constants
#define BS   2
#define Q    300
#define C    91
#define NPRED 600         // BS*Q
#define T    60
#define H    256
#define W    256
#define HW   65536
#define NPAD 640          // padded preds (10 * 64)
#define TPAD 64           // padded targets
#define NSUMS 128         // TPAD * 2 (a,b)
#define KS   64           // K-split slices
#define KLOC (HW / KS)    // 1024 px per slice
#define MTILE 64
#define CHUNK 64

// ---------------- scratch (static device globals; no allocation) -------------
__device__ uint2 g_bits[HW];                       // 512 KB: per-pixel 60 target bits
__device__ float g_pstats[NPRED * 8];              // xmin,ymin,xmax,ymax,psum,negsum
__device__ float g_tstats[T * 8];                  // xmin,ymin,xmax,ymax,tsum
__device__ float g_partial[(size_t)KS * NPAD * NSUMS]; // 21 MB partial sums
__device__ float g_ab[NPRED * NSUMS];              // reduced (a,b) pairs

// ---------------- K1: pack target masks into bitfields -----------------------
__global__ void pack_bits_kernel(const int* __restrict__ tmasks) {
    int px = blockIdx.x * blockDim.x + threadIdx.x;
    if (px >= HW) return;
    unsigned lo = 0u, hi = 0u;
    #pragma unroll
    for (int t = 0; t < 32; t++)
        if (tmasks[t * HW + px] != 0) lo |= (1u << t);
    #pragma unroll
    for (int t = 32; t < T; t++)
        if (tmasks[t * HW + px] != 0) hi |= (1u << (t - 32));
    g_bits[px] = make_uint2(lo, hi);
}

// ---------------- block reduction helpers ------------------------------------
__device__ __forceinline__ float blk_reduce_sum(float v, float* sh) {
    int tid = threadIdx.x;
    sh[tid] = v; __syncthreads();
    for (int s = 128; s > 0; s >>= 1) {
        if (tid < s) sh[tid] += sh[tid + s];
        __syncthreads();
    }
    float r = sh[0]; __syncthreads();
    return r;
}
__device__ __forceinline__ float blk_reduce_max(float v, float* sh) {
    int tid = threadIdx.x;
    sh[tid] = v; __syncthreads();
    for (int s = 128; s > 0; s >>= 1) {
        if (tid < s) sh[tid] = fmaxf(sh[tid], sh[tid + s]);
        __syncthreads();
    }
    float r = sh[0]; __syncthreads();
    return r;
}
__device__ __forceinline__ float blk_reduce_min(float v, float* sh) {
    int tid = threadIdx.x;
    sh[tid] = v; __syncthreads();
    for (int s = 128; s > 0; s >>= 1) {
        if (tid < s) sh[tid] = fminf(sh[tid], sh[tid + s]);
        __syncthreads();
    }
    float r = sh[0]; __syncthreads();
    return r;
}

// ---------------- K2: target mask stats (boxes + tsum) -----------------------
__global__ void tgt_stats_kernel(const int* __restrict__ tmasks) {
    __shared__ float sh[256];
    int t = blockIdx.x, tid = threadIdx.x;
    const int* row = tmasks + (size_t)t * HW;
    float xmin = 1e8f, ymin = 1e8f, xmax = -1e30f, ymax = -1e30f, ts = 0.f;
    for (int px = tid; px < HW; px += 256) {
        float m = (float)row[px];
        float x = (float)(px & 255), y = (float)(px >> 8);
        float mx = m * x, my = m * y;
        xmax = fmaxf(xmax, mx);
        ymax = fmaxf(ymax, my);
        if (m != 0.f) { xmin = fminf(xmin, mx); ymin = fminf(ymin, my); }
        ts += m;
    }
    float rxmin = blk_reduce_min(xmin, sh);
    float rymin = blk_reduce_min(ymin, sh);
    float rxmax = blk_reduce_max(xmax, sh);
    float rymax = blk_reduce_max(ymax, sh);
    float rts   = blk_reduce_sum(ts, sh);
    if (tid == 0) {
        g_tstats[t * 8 + 0] = rxmin;
        g_tstats[t * 8 + 1] = rymin;
        g_tstats[t * 8 + 2] = rxmax;
        g_tstats[t * 8 + 3] = rymax;
        g_tstats[t * 8 + 4] = rts;
    }
}

// ---------------- K3: pred mask stats (boxes + psum + negsum) ----------------
__global__ void pred_stats_kernel(const float* __restrict__ pmasks) {
    __shared__ float sh[256];
    int n = blockIdx.x, tid = threadIdx.x;
    const float* row = pmasks + (size_t)n * HW;
    float xmin = 1e8f, ymin = 1e8f, xmax = -1e30f, ymax = -1e30f;
    float ps = 0.f, ns = 0.f;
    for (int px = tid; px < HW; px += 256) {
        float m = row[px];
        float x = (float)(px & 255), y = (float)(px >> 8);
        float mx = m * x, my = m * y;
        xmax = fmaxf(xmax, mx);
        ymax = fmaxf(ymax, my);
        if (m != 0.f) { xmin = fminf(xmin, mx); ymin = fminf(ymin, my); }
        float e = __expf(-m);
        float p = 1.f / (1.f + e);
        float q = e * p;                 // 1 - p
        ps += p;
        ns += 0.75f * p * p * (-__logf(q));
    }
    float rxmin = blk_reduce_min(xmin, sh);
    float rymin = blk_reduce_min(ymin, sh);
    float rxmax = blk_reduce_max(xmax, sh);
    float rymax = blk_reduce_max(ymax, sh);
    float rps   = blk_reduce_sum(ps, sh);
    float rns   = blk_reduce_sum(ns, sh);
    if (tid == 0) {
        g_pstats[n * 8 + 0] = rxmin;
        g_pstats[n * 8 + 1] = rymin;
        g_pstats[n * 8 + 2] = rxmax;
        g_pstats[n * 8 + 3] = rymax;
        g_pstats[n * 8 + 4] = rps;
        g_pstats[n * 8 + 5] = rns;
    }
}

// ---------------- K4: fused pairwise "GEMM" (a = s.t, b = (pos-neg).t) -------
__global__ void __launch_bounds__(256) gemm_kernel(const float* __restrict__ pmasks) {
    __shared__ float sS[CHUNK * 65];
    __shared__ float sD[CHUNK * 65];
    __shared__ uint2 sB[CHUNK];

    int mtile = blockIdx.x;       // 0..9
    int ks    = blockIdx.y;       // 0..63
    int tid   = threadIdx.x;
    int tm = tid >> 4;            // 0..15 -> preds tm*4 .. tm*4+3
    int tn = tid & 15;            // 0..15 -> targets tn*4 .. tn*4+3
    int m0 = tm * 4;
    int sh = (tn & 7) * 4;
    bool useHi = (tn >= 8);

    float aa[4][4];
    float bb[4][4];
    #pragma unroll
    for (int i = 0; i < 4; i++)
        #pragma unroll
        for (int j = 0; j < 4; j++) { aa[i][j] = 0.f; bb[i][j] = 0.f; }

    int pxbase = ks * KLOC;
    for (int c = 0; c < KLOC / CHUNK; c++) {
        int px0 = pxbase + c * CHUNK;
        // --- stage A tile: compute s = sigmoid(m), d = pos_px - neg_px ---
        #pragma unroll
        for (int e = tid; e < MTILE * CHUNK; e += 256) {
            int nl = e >> 6, pl = e & 63;
            int n = mtile * MTILE + nl;
            float s = 0.f, d = 0.f;
            if (n < NPRED) {
                float m = pmasks[(size_t)n * HW + px0 + pl];
                float ex = __expf(-m);
                float p = 1.f / (1.f + ex);
                float q = ex * p;
                float lp = __logf(p);
                float lq = __logf(q);
                s = p;
                d = 0.25f * q * q * (-lp) - 0.75f * p * p * (-lq);
            }
            sS[pl * 65 + nl] = s;
            sD[pl * 65 + nl] = d;
        }
        if (tid < CHUNK) sB[tid] = g_bits[px0 + tid];
        __syncthreads();

        // --- accumulate ---
        #pragma unroll 2
        for (int px = 0; px < CHUNK; px++) {
            uint2 w = sB[px];
            unsigned nib = ((useHi ? w.y : w.x) >> sh) & 15u;
            float s0 = sS[px * 65 + m0 + 0];
            float s1 = sS[px * 65 + m0 + 1];
            float s2 = sS[px * 65 + m0 + 2];
            float s3 = sS[px * 65 + m0 + 3];
            float d0 = sD[px * 65 + m0 + 0];
            float d1 = sD[px * 65 + m0 + 1];
            float d2 = sD[px * 65 + m0 + 2];
            float d3 = sD[px * 65 + m0 + 3];
            float f0 = (nib & 1u) ? 1.f : 0.f;
            float f1 = (nib & 2u) ? 1.f : 0.f;
            float f2 = (nib & 4u) ? 1.f : 0.f;
            float f3 = (nib & 8u) ? 1.f : 0.f;
            aa[0][0] = fmaf(f0, s0, aa[0][0]); aa[1][0] = fmaf(f0, s1, aa[1][0]);
            aa[2][0] = fmaf(f0, s2, aa[2][0]); aa[3][0] = fmaf(f0, s3, aa[3][0]);
            bb[0][0] = fmaf(f0, d0, bb[0][0]); bb[1][0] = fmaf(f0, d1, bb[1][0]);
            bb[2][0] = fmaf(f0, d2, bb[2][0]); bb[3][0] = fmaf(f0, d3, bb[3][0]);
            aa[0][1] = fmaf(f1, s0, aa[0][1]); aa[1][1] = fmaf(f1, s1, aa[1][1]);
            aa[2][1] = fmaf(f1, s2, aa[2][1]); aa[3][1] = fmaf(f1, s3, aa[3][1]);
            bb[0][1] = fmaf(f1, d0, bb[0][1]); bb[1][1] = fmaf(f1, d1, bb[1][1]);
            bb[2][1] = fmaf(f1, d2, bb[2][1]); bb[3][1] = fmaf(f1, d3, bb[3][1]);
            aa[0][2] = fmaf(f2, s0, aa[0][2]); aa[1][2] = fmaf(f2, s1, aa[1][2]);
            aa[2][2] = fmaf(f2, s2, aa[2][2]); aa[3][2] = fmaf(f2, s3, aa[3][2]);
            bb[0][2] = fmaf(f2, d0, bb[0][2]); bb[1][2] = fmaf(f2, d1, bb[1][2]);
            bb[2][2] = fmaf(f2, d2, bb[2][2]); bb[3][2] = fmaf(f2, d3, bb[3][2]);
            aa[0][3] = fmaf(f3, s0, aa[0][3]); aa[1][3] = fmaf(f3, s1, aa[1][3]);
            aa[2][3] = fmaf(f3, s2, aa[2][3]); aa[3][3] = fmaf(f3, s3, aa[3][3]);
            bb[0][3] = fmaf(f3, d0, bb[0][3]); bb[1][3] = fmaf(f3, d1, bb[1][3]);
            bb[2][3] = fmaf(f3, d2, bb[2][3]); bb[3][3] = fmaf(f3, d3, bb[3][3]);
        }
        __syncthreads();
    }

    // write partials
    float* base = g_partial + ((size_t)ks * NPAD + (size_t)mtile * MTILE) * NSUMS;
    #pragma unroll
    for (int mi = 0; mi < 4; mi++) {
        int nl = m0 + mi;
        #pragma unroll
        for (int j = 0; j < 4; j++) {
            int t = tn * 4 + j;
            base[nl * NSUMS + t * 2 + 0] = aa[mi][j];
            base[nl * NSUMS + t * 2 + 1] = bb[mi][j];
        }
    }
}

// ---------------- K5: deterministic partial reduction ------------------------
__global__ void reduce_kernel() {
    int idx = blockIdx.x * blockDim.x + threadIdx.x;
    if (idx >= NPRED * NSUMS) return;
    int n = idx >> 7, si = idx & 127;
    float s = 0.f;
    #pragma unroll 8
    for (int ks = 0; ks < KS; ks++)
        s += g_partial[((size_t)ks * NPAD + n) * NSUMS + si];
    g_ab[idx] = s;
}

// ---------------- K6: final cost assembly ------------------------------------
__device__ __forceinline__ float4 cxcywh_to_xyxy(float4 b) {
    return make_float4(b.x - 0.5f * b.z, b.y - 0.5f * b.w,
                       b.x + 0.5f * b.z, b.y + 0.5f * b.w);
}
__device__ __forceinline__ float giou(float4 A, float4 B) {
    float area1 = (A.z - A.x) * (A.w - A.y);
    float area2 = (B.z - B.x) * (B.w - B.y);
    float ltx = fmaxf(A.x, B.x), lty = fmaxf(A.y, B.y);
    float rbx = fminf(A.z, B.z), rby = fminf(A.w, B.w);
    float w = fmaxf(rbx - ltx, 0.f), h = fmaxf(rby - lty, 0.f);
    float inter = w * h;
    float uni = area1 + area2 - inter;
    float iou = inter / uni;
    float ex = fminf(A.x, B.x), ey = fminf(A.y, B.y);
    float ex2 = fmaxf(A.z, B.z), ey2 = fmaxf(A.w, B.w);
    float we = fmaxf(ex2 - ex, 0.f), he = fmaxf(ey2 - ey, 0.f);
    float ae = we * he;
    return iou - (ae - uni) / ae;
}

__global__ void final_kernel(const float* __restrict__ logits,
                             const float* __restrict__ pboxes,
                             const float* __restrict__ tboxes,
                             const int* __restrict__ tids,
                             float* __restrict__ out) {
    int n = blockIdx.x;
    int t = threadIdx.x;
    if (t >= T) return;

    // focal classification cost
    int id = tids[t];
    float L = logits[n * C + id];
    float p = 1.f / (1.f + expf(-L));
    float pos_cc = 0.25f * (1.f - p) * (1.f - p) * (-logf(p + 1e-8f));
    float neg_cc = 0.75f * p * p * (-logf(1.f - p + 1e-8f));
    float cc = pos_cc - neg_cc;

    // L1 box cost
    float4 pb = reinterpret_cast<const float4*>(pboxes)[n];
    float4 tb = reinterpret_cast<const float4*>(tboxes)[t];
    float cb = fabsf(pb.x - tb.x) + fabsf(pb.y - tb.y) +
               fabsf(pb.z - tb.z) + fabsf(pb.w - tb.w);

    // GIoU box cost
    float cg = -giou(cxcywh_to_xyxy(pb), cxcywh_to_xyxy(tb));

    // GIoU on mask-derived boxes (stats stored as xmin,ymin,xmax,ymax; the
    // reference re-applies cxcywh->xyxy on them, faithfully mirrored)
    float4 pm4 = make_float4(g_pstats[n * 8 + 0], g_pstats[n * 8 + 1],
                             g_pstats[n * 8 + 2], g_pstats[n * 8 + 3]);
    float4 tm4 = make_float4(g_tstats[t * 8 + 0], g_tstats[t * 8 + 1],
                             g_tstats[t * 8 + 2], g_tstats[t * 8 + 3]);
    float cgm = -giou(cxcywh_to_xyxy(pm4), cxcywh_to_xyxy(tm4));

    // dice + focal mask costs
    float a = g_ab[n * NSUMS + t * 2 + 0];
    float b = g_ab[n * NSUMS + t * 2 + 1];
    float psum = g_pstats[n * 8 + 4];
    float nsum = g_pstats[n * 8 + 5];
    float tsum = g_tstats[t * 8 + 4];
    float dice = 1.f - (2.f * a + 1e-5f) / (psum + tsum + 1e-5f);
    float foc = (b + nsum) * (1.f / 65536.f);

    out[n * T + t] = cb + cc + cg + cgm + dice + foc;
}

// ---------------- launch ------------------------------------------------------
extern "C" void kernel_launch(void* const* d_in, const int* in_sizes, int n_in,
                              void* d_out, int out_size) {
    const float* pred_logits = (const float*)d_in[0];
    const float* pred_boxes  = (const float*)d_in[1];
    const float* pred_masks  = (const float*)d_in[2];
    const float* tgt_boxes   = (const float*)d_in[3];
    const int*   tgt_ids     = (const int*)d_in[4];
    const int*   tgt_masks   = (const int*)d_in[5];
    float* out = (float*)d_out;

    pack_bits_kernel<<<HW / 256, 256>>>(tgt_masks);
    tgt_stats_kernel<<<T, 256>>>(tgt_masks);
    pred_stats_kernel<<<NPRED, 256>>>(pred_masks);
    gemm_kernel<<<dim3(NPAD / MTILE, KS), 256>>>(pred_masks);
    reduce_kernel<<<(NPRED * NSUMS + 255) / 256, 256>>>();
    final_kernel<<<NPRED, 64>>>(pred_logits, pred_boxes, tgt_boxes, tgt_ids, out);
}

// round 4
// speedup vs baseline: 4.9168x; 4.9168x over previous
#include <cuda_runtime.h>
#include <cuda_bf16.h>
#include <cstdint>

// Problem constants
#define NPRED 600
#define T     60
#define C     91
#define HW    65536
#define MROWS 1280          // 640 s-rows + 640 d-rows
#define TPAD  64
#define KSLICES 32
#define KLOC  2048          // K per slice
#define KC    64            // K chunk (pixels)
#define NCHUNK (KLOC / KC)  // 32
#define TSEG  8

// ---------------- scratch (static device globals; no allocation) -------------
__device__ __nv_bfloat16 g_B[(size_t)TPAD * HW];            // 8 MB; rows 60..63 stay 0
__device__ float g_part[(size_t)KSLICES * MROWS * TPAD];    // 10.5 MB GEMM partials
__device__ float g_ab[(size_t)MROWS * TPAD];
__device__ float g_spart[(size_t)KSLICES * 640 * 8];        // pred stat partials
__device__ float g_tpart[(size_t)TSEG * T * 8];             // tgt stat partials
__device__ float g_pstats[NPRED * 8];
__device__ float g_tstats[T * 8];

// ---------------- PTX helpers (all plain-sm_100 legal) ------------------------
__device__ __forceinline__ void ldsm4(uint32_t& r0, uint32_t& r1, uint32_t& r2,
                                      uint32_t& r3, uint32_t addr) {
    asm volatile("ldmatrix.sync.aligned.m8n8.x4.shared.b16 {%0,%1,%2,%3}, [%4];"
                 : "=r"(r0), "=r"(r1), "=r"(r2), "=r"(r3) : "r"(addr));
}
__device__ __forceinline__ void mma16816(float* c, uint32_t a0, uint32_t a1,
                                         uint32_t a2, uint32_t a3,
                                         uint32_t b0, uint32_t b1) {
    asm volatile(
        "mma.sync.aligned.m16n8k16.row.col.f32.bf16.bf16.f32 "
        "{%0,%1,%2,%3}, {%4,%5,%6,%7}, {%8,%9}, {%0,%1,%2,%3};"
        : "+f"(c[0]), "+f"(c[1]), "+f"(c[2]), "+f"(c[3])
        : "r"(a0), "r"(a1), "r"(a2), "r"(a3), "r"(b0), "r"(b1));
}
#define CPA16(dst, src) \
    asm volatile("cp.async.cg.shared.global [%0], [%1], 16;" :: "r"(dst), "l"(src))

// ---------------- block reduction helpers ------------------------------------
__device__ __forceinline__ float blk_reduce_sum(float v, float* sh) {
    int tid = threadIdx.x;
    sh[tid] = v; __syncthreads();
    for (int s = 128; s > 0; s >>= 1) {
        if (tid < s) sh[tid] += sh[tid + s];
        __syncthreads();
    }
    float r = sh[0]; __syncthreads();
    return r;
}
__device__ __forceinline__ float blk_reduce_max(float v, float* sh) {
    int tid = threadIdx.x;
    sh[tid] = v; __syncthreads();
    for (int s = 128; s > 0; s >>= 1) {
        if (tid < s) sh[tid] = fmaxf(sh[tid], sh[tid + s]);
        __syncthreads();
    }
    float r = sh[0]; __syncthreads();
    return r;
}
__device__ __forceinline__ float blk_reduce_min(float v, float* sh) {
    int tid = threadIdx.x;
    sh[tid] = v; __syncthreads();
    for (int s = 128; s > 0; s >>= 1) {
        if (tid < s) sh[tid] = fminf(sh[tid], sh[tid + s]);
        __syncthreads();
    }
    float r = sh[0]; __syncthreads();
    return r;
}

// ---------------- K1: target stats + bf16 B matrix (segmented) ---------------
__global__ void tgt_kernel(const int* __restrict__ tmasks) {
    __shared__ float sh[256];
    int t = blockIdx.x, seg = blockIdx.y, tid = threadIdx.x;
    const int4* row = (const int4*)(tmasks + (size_t)t * HW + seg * 8192);
    __nv_bfloat162* brow = (__nv_bfloat162*)(g_B + (size_t)t * HW + seg * 8192);
    float xmin = 1e8f, ymin = 1e8f, xmax = -1e30f, ymax = -1e30f, ts = 0.f;
    for (int i = tid; i < 2048; i += 256) {
        int4 v = row[i];
        int px0 = seg * 8192 + i * 4;
        float mv[4] = {(float)v.x, (float)v.y, (float)v.z, (float)v.w};
        #pragma unroll
        for (int j = 0; j < 4; j++) {
            float m = mv[j];
            int px = px0 + j;
            float x = (float)(px & 255), y = (float)(px >> 8);
            float mx = m * x, my = m * y;
            xmax = fmaxf(xmax, mx);
            ymax = fmaxf(ymax, my);
            if (m != 0.f) { xmin = fminf(xmin, mx); ymin = fminf(ymin, my); }
            ts += m;
        }
        __nv_bfloat162 h0, h1;
        h0.x = __float2bfloat16_rn(mv[0]); h0.y = __float2bfloat16_rn(mv[1]);
        h1.x = __float2bfloat16_rn(mv[2]); h1.y = __float2bfloat16_rn(mv[3]);
        brow[i * 2 + 0] = h0;
        brow[i * 2 + 1] = h1;
    }
    float rxmin = blk_reduce_min(xmin, sh);
    float rymin = blk_reduce_min(ymin, sh);
    float rxmax = blk_reduce_max(xmax, sh);
    float rymax = blk_reduce_max(ymax, sh);
    float rts   = blk_reduce_sum(ts, sh);
    if (tid == 0) {
        float* o = g_tpart + ((size_t)seg * T + t) * 8;
        o[0] = rxmin; o[1] = rymin; o[2] = rxmax; o[3] = rymax; o[4] = rts;
    }
}

// ---------------- K2: fused transform + stats + bf16 MMA GEMM ----------------
// Block: 64 preds (=128 A rows: s + d) x 64 targets x K-slice of 2048.
// smem: sA[2][128x128B] at 0..32768, sB[2][64x128B] at 32768..49152.
__global__ void __launch_bounds__(256) fused_kernel(const float* __restrict__ pmasks) {
    __shared__ __align__(1024) char smem[49152];
    uint32_t sb = (uint32_t)__cvta_generic_to_shared(smem);
    int tid = threadIdx.x, lane = tid & 31, wid = tid >> 5;
    int wm = wid >> 1, wn = wid & 1;
    int mtile = blockIdx.x, ksl = blockIdx.y;

    // compute-role mapping: 4 threads per pred row, 16 px each per chunk
    int pr = tid >> 2, q = tid & 3;
    int pred = mtile * 64 + pr;
    bool valid = pred < NPRED;
    const float* aSrc = pmasks + (size_t)pred * HW + (size_t)ksl * KLOC + q * 16;

    // B cp.async mapping: row btr, two 16B granules per thread
    int btr = tid >> 2;
    int bg0 = tid & 3;
    int bx = btr & 7;
    const char* bSrc = (const char*)g_B + (size_t)btr * (HW * 2) + (size_t)ksl * (KLOC * 2);

    // ldmatrix lane addressing (byte offsets inside smem)
    int srow = (lane & 7) + ((lane >> 3) & 1) * 8;
    int ghi  = lane >> 4;
    int ra0 = wm * 32 + srow, ra1 = ra0 + 16;
    int rb0 = wn * 32 + srow, rb1 = rb0 + 16;
    int offA0 = ra0 * 128, xa0 = ra0 & 7;
    int offA1 = ra1 * 128, xa1 = ra1 & 7;
    int offB0 = 32768 + rb0 * 128, xb0 = rb0 & 7;
    int offB1 = 32768 + rb1 * 128, xb1 = rb1 & 7;

    // sA store offsets: s row = pr, d row = 64+pr; granules 2q, 2q+1
    int rs = pr, rd = 64 + pr;
    int oS0 = rs * 128 + (((2 * q)     ^ (rs & 7)) << 4);
    int oS1 = rs * 128 + (((2 * q + 1) ^ (rs & 7)) << 4);
    int oD0 = rd * 128 + (((2 * q)     ^ (rd & 7)) << 4);
    int oD1 = rd * 128 + (((2 * q + 1) ^ (rd & 7)) << 4);

    float acc[2][4][4];
    #pragma unroll
    for (int mi = 0; mi < 2; mi++)
        #pragma unroll
        for (int ni = 0; ni < 4; ni++)
            #pragma unroll
            for (int e = 0; e < 4; e++) acc[mi][ni][e] = 0.f;

    float xmin = 1e8f, ymin = 1e8f, xmax = -1e30f, ymax = -1e30f;
    float ps = 0.f, ns = 0.f;

    // prologue: B chunk 0 -> buf0; A chunk 0 -> regs
    {
        uint32_t bd = sb + 32768 + (uint32_t)(btr * 128);
        CPA16(bd + (uint32_t)(((bg0    ) ^ bx) << 4), bSrc + bg0 * 16);
        CPA16(bd + (uint32_t)(((bg0 + 4) ^ bx) << 4), bSrc + (bg0 + 4) * 16);
        asm volatile("cp.async.commit_group;" ::: "memory");
    }
    float4 mv[4] = {{0,0,0,0},{0,0,0,0},{0,0,0,0},{0,0,0,0}};
    if (valid) {
        #pragma unroll
        for (int i = 0; i < 4; i++)
            mv[i] = *(const float4*)(aSrc + i * 4);
    }

    int pxq = ksl * KLOC + q * 16;   // global px of this thread's first pixel

    for (int c = 0; c < NCHUNK; c++) {
        int bufA = (c & 1) * 16384;
        int bufB = (c & 1) * 8192;

        // ---- 1. transform chunk c (regs) -> bf16 sA + stats ----
        float sv[16], dv[16];
        #pragma unroll
        for (int i = 0; i < 4; i++) {
            float m4[4] = {mv[i].x, mv[i].y, mv[i].z, mv[i].w};
            #pragma unroll
            for (int j = 0; j < 4; j++) {
                float m = m4[j];
                int px = pxq + c * 64 + i * 4 + j;
                float x = (float)(px & 255), y = (float)(px >> 8);
                float mx = m * x, my = m * y;
                xmax = fmaxf(xmax, mx);
                ymax = fmaxf(ymax, my);
                if (m != 0.f) { xmin = fminf(xmin, mx); ymin = fminf(ymin, my); }
                float e = __expf(-m);
                float tt = 1.f + e;
                float p = __fdividef(1.f, tt);
                float qq = e * p;                 // 1 - p
                float lp = -__logf(tt);           // log p
                float lq = lp - m;                // log(1-p)
                float pos = -0.25f * qq * qq * lp;
                float neg = -0.75f * p * p * lq;
                ps += p;
                ns += neg;
                sv[i * 4 + j] = p;
                dv[i * 4 + j] = pos - neg;
            }
        }
        uint32_t us[8], ud[8];
        #pragma unroll
        for (int k = 0; k < 8; k++) {
            __nv_bfloat162 hs, hd;
            hs.x = __float2bfloat16_rn(sv[2 * k]); hs.y = __float2bfloat16_rn(sv[2 * k + 1]);
            hd.x = __float2bfloat16_rn(dv[2 * k]); hd.y = __float2bfloat16_rn(dv[2 * k + 1]);
            us[k] = *(uint32_t*)&hs;
            ud[k] = *(uint32_t*)&hd;
        }
        *(uint4*)(smem + bufA + oS0) = make_uint4(us[0], us[1], us[2], us[3]);
        *(uint4*)(smem + bufA + oS1) = make_uint4(us[4], us[5], us[6], us[7]);
        *(uint4*)(smem + bufA + oD0) = make_uint4(ud[0], ud[1], ud[2], ud[3]);
        *(uint4*)(smem + bufA + oD1) = make_uint4(ud[4], ud[5], ud[6], ud[7]);

        // ---- 2. B(c) resident, publish tiles ----
        asm volatile("cp.async.wait_group 0;" ::: "memory");
        __syncthreads();

        // ---- 3. prefetch B(c+1) + A(c+1) ----
        if (c + 1 < NCHUNK) {
            uint32_t bd = sb + 32768 + (uint32_t)(((c + 1) & 1) * 8192 + btr * 128);
            const char* bs = bSrc + (c + 1) * 128;
            CPA16(bd + (uint32_t)(((bg0    ) ^ bx) << 4), bs + bg0 * 16);
            CPA16(bd + (uint32_t)(((bg0 + 4) ^ bx) << 4), bs + (bg0 + 4) * 16);
            asm volatile("cp.async.commit_group;" ::: "memory");
            if (valid) {
                #pragma unroll
                for (int i = 0; i < 4; i++)
                    mv[i] = *(const float4*)(aSrc + (c + 1) * 64 + i * 4);
            }
        }

        // ---- 4. MMA over 4 k16 steps ----
        #pragma unroll
        for (int ks = 0; ks < 4; ks++) {
            uint32_t a0, a1, a2, a3, a4, a5, a6, a7;
            uint32_t b00, b01, b02, b03, b10, b11, b12, b13;
            int g = 2 * ks + ghi;
            ldsm4(a0, a1, a2, a3, sb + bufA + offA0 + ((g ^ xa0) << 4));
            ldsm4(a4, a5, a6, a7, sb + bufA + offA1 + ((g ^ xa1) << 4));
            ldsm4(b00, b01, b02, b03, sb + bufB + offB0 + ((g ^ xb0) << 4));
            ldsm4(b10, b11, b12, b13, sb + bufB + offB1 + ((g ^ xb1) << 4));
            mma16816(acc[0][0], a0, a1, a2, a3, b00, b02);
            mma16816(acc[0][1], a0, a1, a2, a3, b01, b03);
            mma16816(acc[0][2], a0, a1, a2, a3, b10, b12);
            mma16816(acc[0][3], a0, a1, a2, a3, b11, b13);
            mma16816(acc[1][0], a4, a5, a6, a7, b00, b02);
            mma16816(acc[1][1], a4, a5, a6, a7, b01, b03);
            mma16816(acc[1][2], a4, a5, a6, a7, b10, b12);
            mma16816(acc[1][3], a4, a5, a6, a7, b11, b13);
        }
        __syncthreads();
    }

    // ---- epilogue: GEMM partials ----
    #pragma unroll
    for (int mi = 0; mi < 2; mi++) {
        int la = wm * 32 + mi * 16 + (lane >> 2);
        #pragma unroll
        for (int half = 0; half < 2; half++) {
            int larow = la + half * 8;
            int grow = (larow < 64) ? (mtile * 64 + larow) : (576 + mtile * 64 + larow);
            float* dst = g_part + ((size_t)ksl * MROWS + grow) * TPAD;
            #pragma unroll
            for (int ni = 0; ni < 4; ni++) {
                int n0 = wn * 32 + ni * 8 + (lane & 3) * 2;
                dst[n0 + 0] = acc[mi][ni][half * 2 + 0];
                dst[n0 + 1] = acc[mi][ni][half * 2 + 1];
            }
        }
    }

    // ---- epilogue: stats (reduce 4 threads per pred row via shfl) ----
    #pragma unroll
    for (int off = 1; off <= 2; off <<= 1) {
        xmin = fminf(xmin, __shfl_xor_sync(0xffffffffu, xmin, off));
        ymin = fminf(ymin, __shfl_xor_sync(0xffffffffu, ymin, off));
        xmax = fmaxf(xmax, __shfl_xor_sync(0xffffffffu, xmax, off));
        ymax = fmaxf(ymax, __shfl_xor_sync(0xffffffffu, ymax, off));
        ps += __shfl_xor_sync(0xffffffffu, ps, off);
        ns += __shfl_xor_sync(0xffffffffu, ns, off);
    }
    if (q == 0) {
        float* o = g_spart + ((size_t)ksl * 640 + mtile * 64 + pr) * 8;
        o[0] = xmin; o[1] = ymin; o[2] = xmax; o[3] = ymax; o[4] = ps; o[5] = ns;
    }
}

// ---------------- K3: deterministic reductions --------------------------------
__global__ void reduce_ab() {
    int i = blockIdx.x * blockDim.x + threadIdx.x;   // 0..MROWS*TPAD-1
    float s = 0.f;
    #pragma unroll
    for (int k = 0; k < KSLICES; k++)
        s += g_part[(size_t)k * MROWS * TPAD + i];
    g_ab[i] = s;
}

__global__ void reduce_stats() {
    int idx = blockIdx.x * blockDim.x + threadIdx.x;
    if (idx < NPRED) {
        float xmin = 1e8f, ymin = 1e8f, xmax = -1e30f, ymax = -1e30f;
        float ps = 0.f, ns = 0.f;
        for (int k = 0; k < KSLICES; k++) {
            const float* o = g_spart + ((size_t)k * 640 + idx) * 8;
            xmin = fminf(xmin, o[0]); ymin = fminf(ymin, o[1]);
            xmax = fmaxf(xmax, o[2]); ymax = fmaxf(ymax, o[3]);
            ps += o[4]; ns += o[5];
        }
        float* d = g_pstats + idx * 8;
        d[0] = xmin; d[1] = ymin; d[2] = xmax; d[3] = ymax; d[4] = ps; d[5] = ns;
    } else if (idx < NPRED + T) {
        int t = idx - NPRED;
        float xmin = 1e8f, ymin = 1e8f, xmax = -1e30f, ymax = -1e30f, ts = 0.f;
        for (int k = 0; k < TSEG; k++) {
            const float* o = g_tpart + ((size_t)k * T + t) * 8;
            xmin = fminf(xmin, o[0]); ymin = fminf(ymin, o[1]);
            xmax = fmaxf(xmax, o[2]); ymax = fmaxf(ymax, o[3]);
            ts += o[4];
        }
        float* d = g_tstats + t * 8;
        d[0] = xmin; d[1] = ymin; d[2] = xmax; d[3] = ymax; d[4] = ts;
    }
}

// ---------------- K4: final cost assembly ------------------------------------
__device__ __forceinline__ float4 cxcywh_to_xyxy(float4 b) {
    return make_float4(b.x - 0.5f * b.z, b.y - 0.5f * b.w,
                       b.x + 0.5f * b.z, b.y + 0.5f * b.w);
}
__device__ __forceinline__ float giou(float4 A, float4 B) {
    float area1 = (A.z - A.x) * (A.w - A.y);
    float area2 = (B.z - B.x) * (B.w - B.y);
    float ltx = fmaxf(A.x, B.x), lty = fmaxf(A.y, B.y);
    float rbx = fminf(A.z, B.z), rby = fminf(A.w, B.w);
    float w = fmaxf(rbx - ltx, 0.f), h = fmaxf(rby - lty, 0.f);
    float inter = w * h;
    float uni = area1 + area2 - inter;
    float iou = inter / uni;
    float ex = fminf(A.x, B.x), ey = fminf(A.y, B.y);
    float ex2 = fmaxf(A.z, B.z), ey2 = fmaxf(A.w, B.w);
    float we = fmaxf(ex2 - ex, 0.f), he = fmaxf(ey2 - ey, 0.f);
    float ae = we * he;
    return iou - (ae - uni) / ae;
}

__global__ void final_kernel(const float* __restrict__ logits,
                             const float* __restrict__ pboxes,
                             const float* __restrict__ tboxes,
                             const int* __restrict__ tids,
                             float* __restrict__ out) {
    int n = blockIdx.x;
    int t = threadIdx.x;
    if (t >= T) return;

    int id = tids[t];
    float L = logits[n * C + id];
    float p = 1.f / (1.f + expf(-L));
    float pos_cc = 0.25f * (1.f - p) * (1.f - p) * (-logf(p + 1e-8f));
    float neg_cc = 0.75f * p * p * (-logf(1.f - p + 1e-8f));
    float cc = pos_cc - neg_cc;

    float4 pb = reinterpret_cast<const float4*>(pboxes)[n];
    float4 tb = reinterpret_cast<const float4*>(tboxes)[t];
    float cb = fabsf(pb.x - tb.x) + fabsf(pb.y - tb.y) +
               fabsf(pb.z - tb.z) + fabsf(pb.w - tb.w);

    float cg = -giou(cxcywh_to_xyxy(pb), cxcywh_to_xyxy(tb));

    float4 pm4 = make_float4(g_pstats[n * 8 + 0], g_pstats[n * 8 + 1],
                             g_pstats[n * 8 + 2], g_pstats[n * 8 + 3]);
    float4 tm4 = make_float4(g_tstats[t * 8 + 0], g_tstats[t * 8 + 1],
                             g_tstats[t * 8 + 2], g_tstats[t * 8 + 3]);
    float cgm = -giou(cxcywh_to_xyxy(pm4), cxcywh_to_xyxy(tm4));

    float a = g_ab[(size_t)n * TPAD + t];
    float b = g_ab[(size_t)(640 + n) * TPAD + t];
    float psum = g_pstats[n * 8 + 4];
    float nsum = g_pstats[n * 8 + 5];
    float tsum = g_tstats[t * 8 + 4];
    float dice = 1.f - (2.f * a + 1e-5f) / (psum + tsum + 1e-5f);
    float foc = (b + nsum) * (1.f / 65536.f);

    out[n * T + t] = cb + cc + cg + cgm + dice + foc;
}

// ---------------- launch ------------------------------------------------------
extern "C" void kernel_launch(void* const* d_in, const int* in_sizes, int n_in,
                              void* d_out, int out_size) {
    const float* pred_logits = (const float*)d_in[0];
    const float* pred_boxes  = (const float*)d_in[1];
    const float* pred_masks  = (const float*)d_in[2];
    const float* tgt_boxes   = (const float*)d_in[3];
    const int*   tgt_ids     = (const int*)d_in[4];
    const int*   tgt_masks   = (const int*)d_in[5];
    float* out = (float*)d_out;

    tgt_kernel<<<dim3(T, TSEG), 256>>>(tgt_masks);
    fused_kernel<<<dim3(10, KSLICES), 256>>>(pred_masks);
    reduce_ab<<<(MROWS * TPAD) / 256, 256>>>();
    reduce_stats<<<3, 256>>>();
    final_kernel<<<NPRED, 64>>>(pred_logits, pred_boxes, tgt_boxes, tgt_ids, out);
}